// round 4
// baseline (speedup 1.0000x reference)
#include <cuda_runtime.h>

#define B_    16
#define CIN_  256
#define COUT_ 3
#define WDIM_ 512
#define INS   128
#define OUTS  256
#define FW    13
#define TR    16      // output rows per upsample tile
#define IR    14      // input rows needed per tile (TR/2 + 6)

// scratch (allocation-free rule: __device__ globals)
__device__ float g_c[B_ * COUT_ * CIN_];          // combined per-(b,o,i) weight
__device__ float g_kf[FW];                        // 2 * reversed filter
__device__ float g_mid[B_ * COUT_ * INS * INS];   // post 1x1 conv + clamp

// ---------------------------------------------------------------------------
// K1: styles + combined weights + filter prep
__global__ void k_styles(const float* __restrict__ w,
                         const float* __restrict__ aw,
                         const float* __restrict__ abias,
                         const float* __restrict__ cw,
                         const float* __restrict__ filt) {
    int b    = blockIdx.x;
    int warp = threadIdx.x >> 5;
    int lane = threadIdx.x & 31;
    const float* wr = w + (size_t)b * WDIM_;
    #pragma unroll
    for (int ii = 0; ii < 4; ii++) {
        int i = blockIdx.y * 32 + warp * 4 + ii;
        const float* awr = aw + (size_t)i * WDIM_;
        float s = 0.f;
        #pragma unroll
        for (int j = lane; j < WDIM_; j += 32)
            s += wr[j] * awr[j];
        #pragma unroll
        for (int off = 16; off; off >>= 1)
            s += __shfl_down_sync(0xffffffffu, s, off);
        if (lane == 0) {
            float style = (s * 0.04419417382415922f /*1/sqrt(512)*/ + abias[i])
                          * 0.0625f /*1/sqrt(256)*/;
            #pragma unroll
            for (int o = 0; o < COUT_; o++)
                g_c[(b * COUT_ + o) * CIN_ + i] = cw[o * CIN_ + i] * style;
        }
    }
    if (blockIdx.x == 0 && blockIdx.y == 0 && threadIdx.x < FW)
        g_kf[threadIdx.x] = 2.0f * filt[FW - 1 - threadIdx.x];
}

// ---------------------------------------------------------------------------
// K2: y[b,o,p] = clip(sum_i x[b,i,p]*c[b,o,i] + bias[o], +-256)
// grid (16 pixel-tiles, 16 b), 256 threads, float4 per thread (1024 px/block)
// unroll 8 on the channel loop -> MLP ~8 per thread, HBM-saturating.
__global__ void k_einsum(const float* __restrict__ x,
                         const float* __restrict__ cbias) {
    const int b    = blockIdx.y;
    const int base = blockIdx.x * 1024 + threadIdx.x * 4;

    __shared__ float c_sm[COUT_ * CIN_];
    for (int t = threadIdx.x; t < (COUT_ * CIN_) / 4; t += 256)
        ((float4*)c_sm)[t] = ((const float4*)(g_c + b * COUT_ * CIN_))[t];
    __syncthreads();

    float4 a0 = make_float4(0.f, 0.f, 0.f, 0.f);
    float4 a1 = a0, a2 = a0;

    const float* xb = x + (size_t)b * CIN_ * INS * INS + base;
    #pragma unroll 8
    for (int i = 0; i < CIN_; i++) {
        float4 v = *(const float4*)(xb + i * (INS * INS));
        float c0 = c_sm[i];
        float c1 = c_sm[CIN_ + i];
        float c2 = c_sm[2 * CIN_ + i];
        a0.x += c0 * v.x; a0.y += c0 * v.y; a0.z += c0 * v.z; a0.w += c0 * v.w;
        a1.x += c1 * v.x; a1.y += c1 * v.y; a1.z += c1 * v.z; a1.w += c1 * v.w;
        a2.x += c2 * v.x; a2.y += c2 * v.y; a2.z += c2 * v.z; a2.w += c2 * v.w;
    }

    float4* mp = (float4*)g_mid;
    float4 accs[3] = {a0, a1, a2};
    #pragma unroll
    for (int o = 0; o < COUT_; o++) {
        float bia = cbias[o];
        float4 r = accs[o];
        r.x = fminf(fmaxf(r.x + bia, -256.f), 256.f);
        r.y = fminf(fmaxf(r.y + bia, -256.f), 256.f);
        r.z = fminf(fmaxf(r.z + bia, -256.f), 256.f);
        r.w = fminf(fmaxf(r.w + bia, -256.f), 256.f);
        mp[(((size_t)(b * COUT_ + o)) * (INS * INS) + base) >> 2] = r;
    }
}

// ---------------------------------------------------------------------------
// K3: fused separable polyphase x2 upsample (H then V, all in shared memory).
// grid (48 planes, 16 row-tiles), 256 threads.
// Tap identity: for output index n (either axis), source base = (n>>1)-3 for
// BOTH parities; even phase weights kf[1,3,..,11] (6 taps), odd kf[0,2,..,12].
__global__ void k_upfused(float* __restrict__ out) {
    const int plane = blockIdx.x;
    const int tile  = blockIdx.y;
    const int r0    = tile * TR;     // first output row
    const int s0    = r0 >> 1;       // first "center" input row
    const int tid   = threadIdx.x;

    __shared__ float kf[FW];
    __shared__ float in_s[IR][INS];
    __shared__ float h_s[IR][OUTS];

    if (tid < FW) kf[tid] = g_kf[tid];

    // stage input rows s0-3 .. s0+10 (zero outside [0,128))
    const float* mp = g_mid + (size_t)plane * INS * INS;
    #pragma unroll
    for (int idx = tid; idx < IR * INS; idx += 256) {
        int r  = idx >> 7;
        int c  = idx & (INS - 1);
        int gr = s0 - 3 + r;
        in_s[r][c] = (gr >= 0 && gr < INS) ? mp[gr * INS + c] : 0.f;
    }
    __syncthreads();

    // ---- horizontal: col n = tid, all IR rows ----
    {
        const int n   = tid;
        const int par = n & 1;
        const int cb  = (n >> 1) - 3;
        float wt[7];
        int   cc[7];
        #pragma unroll
        for (int j = 0; j < 7; j++) {
            int c   = cb + j;
            float v = par ? kf[2 * j] : ((j < 6) ? kf[2 * j + 1] : 0.f);
            bool ok = (c >= 0 && c < INS);
            cc[j] = ok ? c : 0;
            wt[j] = ok ? v : 0.f;
        }
        #pragma unroll
        for (int r = 0; r < IR; r++) {
            float acc = 0.f;
            #pragma unroll
            for (int j = 0; j < 7; j++)
                acc += wt[j] * in_s[r][cc[j]];
            h_s[r][n] = acc;
        }
    }
    __syncthreads();

    // ---- vertical: col = tid, TR output rows ----
    float* op = out + ((size_t)plane * OUTS + r0) * OUTS + tid;
    #pragma unroll
    for (int k = 0; k < TR; k++) {
        const int n2  = r0 + k;
        const int lrb = (n2 >> 1) - s0;   // local base row in h_s
        float acc = 0.f;
        if (n2 & 1) {
            #pragma unroll
            for (int j = 0; j < 7; j++)
                acc += kf[2 * j] * h_s[lrb + j][tid];
        } else {
            #pragma unroll
            for (int j = 0; j < 6; j++)
                acc += kf[2 * j + 1] * h_s[lrb + j][tid];
        }
        op[k * OUTS] = acc;
    }
}

// ---------------------------------------------------------------------------
extern "C" void kernel_launch(void* const* d_in, const int* in_sizes, int n_in,
                              void* d_out, int out_size) {
    const float* x     = (const float*)d_in[0];  // [16,256,128,128]
    const float* w     = (const float*)d_in[1];  // [16,512]
    const float* aw    = (const float*)d_in[2];  // [256,512]
    const float* ab    = (const float*)d_in[3];  // [256]
    const float* cw    = (const float*)d_in[4];  // [3,256,1,1]
    const float* cb    = (const float*)d_in[5];  // [3]
    const float* filt  = (const float*)d_in[6];  // [13]
    float* out = (float*)d_out;                  // [16,3,256,256]

    k_styles<<<dim3(B_, 8), 256>>>(w, aw, ab, cw, filt);
    k_einsum<<<dim3(16, B_), 256>>>(x, cb);
    k_upfused<<<dim3(B_ * COUT_, OUTS / TR), 256>>>(out);
}

// round 5
// speedup vs baseline: 1.1669x; 1.1669x over previous
#include <cuda_runtime.h>

#define B_    16
#define CIN_  256
#define COUT_ 3
#define WDIM_ 512
#define INS   128
#define OUTS  256
#define FW    13
#define TR    16      // output rows per upsample tile
#define IR    14      // input rows needed per tile (TR/2 + 6)

// scratch (allocation-free rule: __device__ globals)
__device__ float g_c[B_ * COUT_ * CIN_];          // combined per-(b,o,i) weight
__device__ float g_kf[FW];                        // 2 * reversed filter
__device__ float g_mid[B_ * COUT_ * INS * INS];   // post 1x1 conv + clamp

// ---- packed f32x2 helpers ---------------------------------------------------
__device__ __forceinline__ unsigned long long pack2(float lo, float hi) {
    unsigned long long r;
    asm("mov.b64 %0, {%1, %2};" : "=l"(r) : "f"(lo), "f"(hi));
    return r;
}
__device__ __forceinline__ void unpack2(unsigned long long v, float& lo, float& hi) {
    asm("mov.b64 {%0, %1}, %2;" : "=f"(lo), "=f"(hi) : "l"(v));
}
#define FFMA2(acc, a, b) \
    asm("fma.rn.f32x2 %0, %1, %2, %0;" : "+l"(acc) : "l"(a), "l"(b))

// ---------------------------------------------------------------------------
// K1: styles + combined weights + filter prep
// one warp per (b,i) dot product: 4096 warps = 512 blocks x 8 warps
__global__ void k_styles(const float* __restrict__ w,
                         const float* __restrict__ aw,
                         const float* __restrict__ abias,
                         const float* __restrict__ cw,
                         const float* __restrict__ filt) {
    const int wg   = blockIdx.x * 8 + (threadIdx.x >> 5);
    const int lane = threadIdx.x & 31;
    const int b    = wg >> 8;
    const int i    = wg & 255;

    const float4* wr4 = (const float4*)(w + (size_t)b * WDIM_);
    const float4* ar4 = (const float4*)(aw + (size_t)i * WDIM_);
    float s = 0.f;
    #pragma unroll
    for (int q = 0; q < 4; q++) {
        float4 a = ar4[q * 32 + lane];
        float4 v = wr4[q * 32 + lane];
        s += a.x * v.x + a.y * v.y + a.z * v.z + a.w * v.w;
    }
    #pragma unroll
    for (int off = 16; off; off >>= 1)
        s += __shfl_down_sync(0xffffffffu, s, off);
    if (lane == 0) {
        float style = (s * 0.04419417382415922f /*1/sqrt(512)*/ + abias[i])
                      * 0.0625f /*1/sqrt(256)*/;
        #pragma unroll
        for (int o = 0; o < COUT_; o++)
            g_c[(b * COUT_ + o) * CIN_ + i] = cw[o * CIN_ + i] * style;
    }
    if (blockIdx.x == 0 && threadIdx.x < FW)
        g_kf[threadIdx.x] = 2.0f * filt[FW - 1 - threadIdx.x];
}

// ---------------------------------------------------------------------------
// K2: y[b,o,p] = clip(sum_i x[b,i,p]*c[b,o,i] + bias[o], +-256)
// packed f32x2 FMA: 6 FFMA2 per warp-iteration instead of 12 scalar FFMA.
// grid (32 px-tiles, 16 b) = 512 blocks, 128 threads, 4 px (float4) / thread.
__global__ void k_einsum(const float* __restrict__ x,
                         const float* __restrict__ cbias) {
    const int b    = blockIdx.y;
    const int base = blockIdx.x * 512 + threadIdx.x * 4;

    // modulation weights, duplicated (c,c) so one LDS.64 = one FFMA2 operand
    __shared__ unsigned long long c2[COUT_ * CIN_];
    for (int t = threadIdx.x; t < COUT_ * CIN_; t += 128) {
        float v = g_c[b * COUT_ * CIN_ + t];
        c2[t] = pack2(v, v);
    }
    __syncthreads();

    unsigned long long a00 = 0ull, a01 = 0ull;   // o=0: (x,y),(z,w)
    unsigned long long a10 = 0ull, a11 = 0ull;   // o=1
    unsigned long long a20 = 0ull, a21 = 0ull;   // o=2

    const float* xb = x + (size_t)b * CIN_ * INS * INS + base;
    #pragma unroll 8
    for (int i = 0; i < CIN_; i++) {
        float4 v = *(const float4*)(xb + i * (INS * INS));
        unsigned long long vlo = pack2(v.x, v.y);
        unsigned long long vhi = pack2(v.z, v.w);
        unsigned long long c0 = c2[i];
        unsigned long long c1 = c2[CIN_ + i];
        unsigned long long ck = c2[2 * CIN_ + i];
        FFMA2(a00, c0, vlo); FFMA2(a01, c0, vhi);
        FFMA2(a10, c1, vlo); FFMA2(a11, c1, vhi);
        FFMA2(a20, ck, vlo); FFMA2(a21, ck, vhi);
    }

    unsigned long long alo[3] = {a00, a10, a20};
    unsigned long long ahi[3] = {a01, a11, a21};
    float4* mp = (float4*)g_mid;
    #pragma unroll
    for (int o = 0; o < COUT_; o++) {
        float bia = cbias[o];
        float4 r;
        unpack2(alo[o], r.x, r.y);
        unpack2(ahi[o], r.z, r.w);
        r.x = fminf(fmaxf(r.x + bia, -256.f), 256.f);
        r.y = fminf(fmaxf(r.y + bia, -256.f), 256.f);
        r.z = fminf(fmaxf(r.z + bia, -256.f), 256.f);
        r.w = fminf(fmaxf(r.w + bia, -256.f), 256.f);
        mp[(((size_t)(b * COUT_ + o)) * (INS * INS) + base) >> 2] = r;
    }
}

// ---------------------------------------------------------------------------
// K3: fused separable polyphase x2 upsample (H then V in shared memory).
// grid (48 planes, 16 row-tiles), 256 threads.
// Source base = (n>>1)-3 for both parities; even phase uses kf[1,3..11],
// odd uses kf[0,2..12]. V stage caches the 14 column values in registers.
__global__ void k_upfused(float* __restrict__ out) {
    const int plane = blockIdx.x;
    const int tile  = blockIdx.y;
    const int r0    = tile * TR;     // first output row (even)
    const int s0    = r0 >> 1;       // first "center" input row
    const int tid   = threadIdx.x;

    __shared__ float kf[FW];
    __shared__ float in_s[IR][INS];
    __shared__ float h_s[IR][OUTS];

    if (tid < FW) kf[tid] = g_kf[tid];

    // stage input rows s0-3 .. s0+10 (zero outside [0,128))
    const float* mp = g_mid + (size_t)plane * INS * INS;
    #pragma unroll
    for (int idx = tid; idx < IR * INS; idx += 256) {
        int r  = idx >> 7;
        int c  = idx & (INS - 1);
        int gr = s0 - 3 + r;
        in_s[r][c] = (gr >= 0 && gr < INS) ? mp[gr * INS + c] : 0.f;
    }
    __syncthreads();

    // ---- horizontal: output col n = tid, all IR rows ----
    {
        const int n   = tid;
        const int par = n & 1;
        const int cb  = (n >> 1) - 3;
        float wt[7];
        int   cc[7];
        #pragma unroll
        for (int j = 0; j < 7; j++) {
            int c   = cb + j;
            float v = par ? kf[2 * j] : ((j < 6) ? kf[2 * j + 1] : 0.f);
            bool ok = (c >= 0 && c < INS);
            cc[j] = ok ? c : 0;
            wt[j] = ok ? v : 0.f;
        }
        #pragma unroll
        for (int r = 0; r < IR; r++) {
            float acc = 0.f;
            #pragma unroll
            for (int j = 0; j < 7; j++)
                acc += wt[j] * in_s[r][cc[j]];
            h_s[r][n] = acc;
        }
    }
    __syncthreads();

    // ---- vertical: col = tid; cache the 14 column samples in registers ----
    float hv[IR];
    #pragma unroll
    for (int r = 0; r < IR; r++) hv[r] = h_s[r][tid];

    float* op = out + ((size_t)plane * OUTS + r0) * OUTS + tid;
    #pragma unroll
    for (int k = 0; k < TR; k++) {
        const int lrb = k >> 1;           // r0 even -> local base row = k>>1
        float acc = 0.f;
        if (k & 1) {
            #pragma unroll
            for (int j = 0; j < 7; j++)
                acc += kf[2 * j] * hv[lrb + j];
        } else {
            #pragma unroll
            for (int j = 0; j < 6; j++)
                acc += kf[2 * j + 1] * hv[lrb + j];
        }
        op[k * OUTS] = acc;
    }
}

// ---------------------------------------------------------------------------
extern "C" void kernel_launch(void* const* d_in, const int* in_sizes, int n_in,
                              void* d_out, int out_size) {
    const float* x     = (const float*)d_in[0];  // [16,256,128,128]
    const float* w     = (const float*)d_in[1];  // [16,512]
    const float* aw    = (const float*)d_in[2];  // [256,512]
    const float* ab    = (const float*)d_in[3];  // [256]
    const float* cw    = (const float*)d_in[4];  // [3,256,1,1]
    const float* cb    = (const float*)d_in[5];  // [3]
    const float* filt  = (const float*)d_in[6];  // [13]
    float* out = (float*)d_out;                  // [16,3,256,256]

    k_styles<<<512, 256>>>(w, aw, ab, cw, filt);
    k_einsum<<<dim3(32, B_), 128>>>(x, cb);
    k_upfused<<<dim3(B_ * COUT_, OUTS / TR), 256>>>(out);
}

// round 8
// speedup vs baseline: 1.3708x; 1.1748x over previous
#include <cuda_runtime.h>

#define B_    16
#define CIN_  256
#define COUT_ 3
#define WDIM_ 512
#define INS   128
#define OUTS  256
#define FW    13
#define TR    16      // output rows per upsample tile
#define IR    14      // input rows needed per tile (TR/2 + 6)
#define CSPL  4       // channel splits in einsum
#define CPB   (CIN_ / CSPL)   // 64 channels per block
#define PLN   (INS * INS)     // 16384 px per plane

// scratch (allocation-free rule: __device__ globals)
__device__ float g_c[B_ * COUT_ * CIN_];               // combined per-(b,o,i) weight
__device__ float g_kf[FW];                             // 2 * reversed filter
__device__ float g_part[CSPL * B_ * COUT_ * PLN];      // unclamped partial sums

// ---- packed f32x2 helpers ---------------------------------------------------
__device__ __forceinline__ unsigned long long pack2(float lo, float hi) {
    unsigned long long r;
    asm("mov.b64 %0, {%1, %2};" : "=l"(r) : "f"(lo), "f"(hi));
    return r;
}
__device__ __forceinline__ void unpack2(unsigned long long v, float& lo, float& hi) {
    asm("mov.b64 {%0, %1}, %2;" : "=f"(lo), "=f"(hi) : "l"(v));
}
#define FFMA2(acc, a, b) \
    asm("fma.rn.f32x2 %0, %1, %2, %0;" : "+l"(acc) : "l"(a), "l"(b))

// ---------------------------------------------------------------------------
// K1: styles + combined weights + filter prep
// one warp per (b,i) dot product: 4096 warps = 512 blocks x 8 warps
__global__ void k_styles(const float* __restrict__ w,
                         const float* __restrict__ aw,
                         const float* __restrict__ abias,
                         const float* __restrict__ cw,
                         const float* __restrict__ filt) {
    const int wg   = blockIdx.x * 8 + (threadIdx.x >> 5);
    const int lane = threadIdx.x & 31;
    const int b    = wg >> 8;
    const int i    = wg & 255;

    const float4* wr4 = (const float4*)(w + (size_t)b * WDIM_);
    const float4* ar4 = (const float4*)(aw + (size_t)i * WDIM_);
    float s = 0.f;
    #pragma unroll
    for (int q = 0; q < 4; q++) {
        float4 a = ar4[q * 32 + lane];
        float4 v = wr4[q * 32 + lane];
        s += a.x * v.x + a.y * v.y + a.z * v.z + a.w * v.w;
    }
    #pragma unroll
    for (int off = 16; off; off >>= 1)
        s += __shfl_down_sync(0xffffffffu, s, off);
    if (lane == 0) {
        float style = (s * 0.04419417382415922f /*1/sqrt(512)*/ + abias[i])
                      * 0.0625f /*1/sqrt(256)*/;
        #pragma unroll
        for (int o = 0; o < COUT_; o++)
            g_c[(b * COUT_ + o) * CIN_ + i] = cw[o * CIN_ + i] * style;
    }
    if (blockIdx.x == 0 && threadIdx.x < FW)
        g_kf[threadIdx.x] = 2.0f * filt[FW - 1 - threadIdx.x];
}

// ---------------------------------------------------------------------------
// K2: split-C partial einsum. Each block reduces 64 channels over 1024 px.
// grid (16 px-tiles, 16 b, 4 csplit), 256 threads, 4 px (float4) / thread.
// 8192 warps total -> DRAM-saturating MLP. No bias/clamp here (moved to K3).
__global__ void k_einsum(const float* __restrict__ x) {
    const int b    = blockIdx.y;
    const int s    = blockIdx.z;
    const int base = blockIdx.x * 1024 + threadIdx.x * 4;

    // 64 channels x 3 outputs of modulation weights, duplicated (c,c)
    __shared__ unsigned long long c2[COUT_ * CPB];
    if (threadIdx.x < COUT_ * CPB) {
        int o = threadIdx.x >> 6;   // /CPB
        int j = threadIdx.x & 63;
        float v = g_c[(b * COUT_ + o) * CIN_ + s * CPB + j];
        c2[threadIdx.x] = pack2(v, v);
    }
    __syncthreads();

    unsigned long long a00 = 0ull, a01 = 0ull;
    unsigned long long a10 = 0ull, a11 = 0ull;
    unsigned long long a20 = 0ull, a21 = 0ull;

    const float* xb = x + ((size_t)b * CIN_ + s * CPB) * PLN + base;
    #pragma unroll 8
    for (int j = 0; j < CPB; j++) {
        float4 v = *(const float4*)(xb + j * PLN);
        unsigned long long vlo = pack2(v.x, v.y);
        unsigned long long vhi = pack2(v.z, v.w);
        unsigned long long c0 = c2[j];
        unsigned long long c1 = c2[CPB + j];
        unsigned long long ck = c2[2 * CPB + j];
        FFMA2(a00, c0, vlo); FFMA2(a01, c0, vhi);
        FFMA2(a10, c1, vlo); FFMA2(a11, c1, vhi);
        FFMA2(a20, ck, vlo); FFMA2(a21, ck, vhi);
    }

    unsigned long long alo[3] = {a00, a10, a20};
    unsigned long long ahi[3] = {a01, a11, a21};
    #pragma unroll
    for (int o = 0; o < COUT_; o++) {
        float4 r;
        unpack2(alo[o], r.x, r.y);
        unpack2(ahi[o], r.z, r.w);
        *(float4*)(g_part + ((size_t)(s * B_ * COUT_ + b * COUT_ + o)) * PLN + base) = r;
    }
}

// ---------------------------------------------------------------------------
// K3: combine partials + bias + clamp, then fused separable polyphase x2
// upsample (H then V in shared memory). grid (48 planes, 16 row-tiles), 256 thr.
__global__ void k_upfused(float* __restrict__ out,
                          const float* __restrict__ cbias) {
    const int plane = blockIdx.x;          // b*3 + o
    const int tile  = blockIdx.y;
    const int r0    = tile * TR;           // first output row (even)
    const int s0    = r0 >> 1;             // first "center" input row
    const int tid   = threadIdx.x;
    const float bia = cbias[plane % COUT_];

    __shared__ float kf[FW];
    __shared__ float in_s[IR][INS];
    __shared__ float h_s[IR][OUTS];

    if (tid < FW) kf[tid] = g_kf[tid];

    // stage input rows s0-3 .. s0+10: sum 4 partials + bias, clamp; 0 outside
    const float* pp = g_part + (size_t)plane * PLN;
    #pragma unroll
    for (int idx = tid; idx < IR * INS; idx += 256) {
        int r  = idx >> 7;
        int c  = idx & (INS - 1);
        int gr = s0 - 3 + r;
        float v = 0.f;
        if (gr >= 0 && gr < INS) {
            int off = gr * INS + c;
            float sum = pp[off]
                      + pp[1 * B_ * COUT_ * PLN + off]
                      + pp[2 * B_ * COUT_ * PLN + off]
                      + pp[3 * B_ * COUT_ * PLN + off];
            v = fminf(fmaxf(sum + bia, -256.f), 256.f);
        }
        in_s[r][c] = v;
    }
    __syncthreads();

    // ---- horizontal: output col n = tid, all IR rows ----
    {
        const int n   = tid;
        const int par = n & 1;
        const int cb  = (n >> 1) - 3;
        float wt[7];
        int   cc[7];
        #pragma unroll
        for (int j = 0; j < 7; j++) {
            int c   = cb + j;
            float v = par ? kf[2 * j] : ((j < 6) ? kf[2 * j + 1] : 0.f);
            bool ok = (c >= 0 && c < INS);
            cc[j] = ok ? c : 0;
            wt[j] = ok ? v : 0.f;
        }
        #pragma unroll
        for (int r = 0; r < IR; r++) {
            float acc = 0.f;
            #pragma unroll
            for (int j = 0; j < 7; j++)
                acc += wt[j] * in_s[r][cc[j]];
            h_s[r][n] = acc;
        }
    }
    __syncthreads();

    // ---- vertical: col = tid; cache the 14 column samples in registers ----
    float hv[IR];
    #pragma unroll
    for (int r = 0; r < IR; r++) hv[r] = h_s[r][tid];

    float* op = out + ((size_t)plane * OUTS + r0) * OUTS + tid;
    #pragma unroll
    for (int k = 0; k < TR; k++) {
        const int lrb = k >> 1;            // r0 even -> local base row = k>>1
        float acc = 0.f;
        if (k & 1) {
            #pragma unroll
            for (int j = 0; j < 7; j++)
                acc += kf[2 * j] * hv[lrb + j];
        } else {
            #pragma unroll
            for (int j = 0; j < 6; j++)
                acc += kf[2 * j + 1] * hv[lrb + j];
        }
        op[k * OUTS] = acc;
    }
}

// ---------------------------------------------------------------------------
extern "C" void kernel_launch(void* const* d_in, const int* in_sizes, int n_in,
                              void* d_out, int out_size) {
    const float* x     = (const float*)d_in[0];  // [16,256,128,128]
    const float* w     = (const float*)d_in[1];  // [16,512]
    const float* aw    = (const float*)d_in[2];  // [256,512]
    const float* ab    = (const float*)d_in[3];  // [256]
    const float* cw    = (const float*)d_in[4];  // [3,256,1,1]
    const float* cb    = (const float*)d_in[5];  // [3]
    const float* filt  = (const float*)d_in[6];  // [13]
    float* out = (float*)d_out;                  // [16,3,256,256]

    k_styles<<<512, 256>>>(w, aw, ab, cw, filt);
    k_einsum<<<dim3(16, B_, CSPL), 256>>>(x);
    k_upfused<<<dim3(B_ * COUT_, OUTS / TR), 256>>>(out, cb);
}